// round 10
// baseline (speedup 1.0000x reference)
#include <cuda_runtime.h>
#include <cuda_fp16.h>
#include <cstdint>

#define N_NODES 40000
#define N_EDGES 640000
#define DF      128
#define N_GRAPHS 128

// ======================= scratch (static device globals) ====================
__device__ float  g_agg[(size_t)N_NODES * DF];
__device__ float  g_h0 [(size_t)N_NODES * DF];
__device__ float  g_h1 [(size_t)N_NODES * DF];
__device__ __half g_hh [(size_t)N_NODES * DF];   // fp16 mirror of current gather source
__device__ float  g_WT [3][DF][256];             // [layer][n][k_cat] transposed weights
__device__ int    g_rowptr[N_NODES + 1];
__device__ int    g_deg [N_NODES];
__device__ int    g_fill[N_NODES];
__device__ int    g_colidx[N_EDGES];
__device__ int    g_bsum[160];
__device__ int    g_boff[160];
__device__ unsigned g_outmax[N_GRAPHS * DF];
__device__ int    g_is64;

// ======================= helpers ===========================================
__device__ __forceinline__ uint32_t f2tf32(float f) {
    uint32_t r;
    asm("cvt.rna.tf32.f32 %0, %1;" : "=r"(r) : "f"(f));
    return r;
}

// mma.sync m16n8k8 tf32: D(4f) = A(4r) * B(2r) + D
#define MMA_TF32(d, a, b0, b1)                                                \
    asm volatile("mma.sync.aligned.m16n8k8.row.col.f32.tf32.tf32.f32 "        \
        "{%0,%1,%2,%3}, {%4,%5,%6,%7}, {%8,%9}, {%0,%1,%2,%3};"               \
        : "+f"((d)[0]), "+f"((d)[1]), "+f"((d)[2]), "+f"((d)[3])              \
        : "r"((a)[0]), "r"((a)[1]), "r"((a)[2]), "r"((a)[3]),                 \
          "r"(b0), "r"(b1))

__device__ __forceinline__ unsigned enc_f(float f) {
    unsigned b = __float_as_uint(f);
    return (b & 0x80000000u) ? ~b : (b | 0x80000000u);
}
__device__ __forceinline__ float dec_f(unsigned u) {
    unsigned b = (u & 0x80000000u) ? (u ^ 0x80000000u) : ~u;
    return __uint_as_float(b);
}
#define ENC_NEG_INF 0x007FFFFFu

// ======================= fused init ========================================
// One kernel: zero deg/fill/outmax, parallel int64 probe, weight transpose,
// and fp16 conversion of x into g_hh. Grid 10000x256 = 2.56M threads.
__global__ void k_init(const int* __restrict__ ew, const float* __restrict__ x,
                       const float* __restrict__ Wrel0, const float* __restrict__ Wroot0,
                       const float* __restrict__ Wrel1, const float* __restrict__ Wroot1,
                       const float* __restrict__ Wrel2, const float* __restrict__ Wroot2) {
    __shared__ int s_any;
    int i = blockIdx.x * blockDim.x + threadIdx.x;

    // x -> half mirror (2.56M half2)
    if (i < N_NODES * DF / 2) {
        float2 v = *((const float2*)x + i);
        *((__half2*)g_hh + i) = __floats2half2_rn(v.x, v.y);
    }
    if (i < N_NODES) { g_deg[i] = 0; g_fill[i] = 0; }
    if (i < N_GRAPHS * DF) g_outmax[i] = ENC_NEG_INF;

    // weight transpose: 3 * 128 * 256 = 98304 elements
    if (i < 3 * DF * 256) {
        int layer = i / (DF * 256);
        int idx = i % (DF * 256);
        const float* Wrel  = (layer == 0) ? Wrel0  : (layer == 1) ? Wrel1  : Wrel2;
        const float* Wroot = (layer == 0) ? Wroot0 : (layer == 1) ? Wroot1 : Wroot2;
        int n = idx >> 8;
        int k = idx & 255;
        g_WT[layer][n][k] = (k < DF) ? Wrel[k * DF + n] : Wroot[(k - DF) * DF + n];
    }

    // parallel probe (block 0): odd words all zero <=> int64 indices
    if (blockIdx.x == 0) {
        if (threadIdx.x == 0) s_any = 0;
        __syncthreads();
        if (ew[2 * threadIdx.x + 1] != 0) atomicOr(&s_any, 1);
        __syncthreads();
        if (threadIdx.x == 0) g_is64 = s_any ? 0 : 1;
    }
}

// ======================= CSR build =========================================
__global__ void k_count(const int* __restrict__ ew) {
    int e = blockIdx.x * blockDim.x + threadIdx.x;
    if (e >= N_EDGES) return;
    int dst = g_is64 ? ew[2 * (N_EDGES + e)] : ew[N_EDGES + e];
    atomicAdd(&g_deg[dst], 1);
}

#define SCAN_BLK 157   // ceil(40000/256)

__global__ void k_scan_part() {
    __shared__ int sh[256];
    int t = threadIdx.x;
    int i = blockIdx.x * 256 + t;
    sh[t] = (i < N_NODES) ? g_deg[i] : 0;
    __syncthreads();
    for (int off = 128; off > 0; off >>= 1) {
        if (t < off) sh[t] += sh[t + off];
        __syncthreads();
    }
    if (t == 0) g_bsum[blockIdx.x] = sh[0];
}

__global__ void k_scan_top() {
    __shared__ int sh[256];
    int t = threadIdx.x;
    int v = (t < SCAN_BLK) ? g_bsum[t] : 0;
    sh[t] = v;
    __syncthreads();
    for (int off = 1; off < 256; off <<= 1) {
        int x = (t >= off) ? sh[t - off] : 0;
        __syncthreads();
        sh[t] += x;
        __syncthreads();
    }
    if (t < SCAN_BLK) g_boff[t] = sh[t] - v;   // exclusive
    if (t == 0) g_rowptr[N_NODES] = N_EDGES;
}

__global__ void k_scan_wr() {
    __shared__ int sh[256];
    int t = threadIdx.x;
    int i = blockIdx.x * 256 + t;
    int v = (i < N_NODES) ? g_deg[i] : 0;
    sh[t] = v;
    __syncthreads();
    for (int off = 1; off < 256; off <<= 1) {
        int x = (t >= off) ? sh[t - off] : 0;
        __syncthreads();
        sh[t] += x;
        __syncthreads();
    }
    if (i < N_NODES) g_rowptr[i] = g_boff[blockIdx.x] + sh[t] - v;
}

__global__ void k_fill(const int* __restrict__ ew) {
    int e = blockIdx.x * blockDim.x + threadIdx.x;
    if (e >= N_EDGES) return;
    int is64 = g_is64;
    int src = is64 ? ew[2 * e] : ew[e];
    int dst = is64 ? ew[2 * (N_EDGES + e)] : ew[N_EDGES + e];
    int pos = atomicAdd(&g_fill[dst], 1);
    g_colidx[g_rowptr[dst] + pos] = src;
}

// ======================= edge aggregation (fp16 gather) ====================
// 1 warp/node; lane covers 4 cols as 2 half2 (one 8B uint2 load per edge).
// Gathers from g_hh (half), accumulates fp32, writes g_agg fp32.
__global__ void __launch_bounds__(256) k_agg() {
    int gwarp = (blockIdx.x * blockDim.x + threadIdx.x) >> 5;
    int lane = threadIdx.x & 31;
    if (gwarp >= N_NODES) return;
    int beg = g_rowptr[gwarp];
    int end = g_rowptr[gwarp + 1];
    float4 acc = make_float4(0.f, 0.f, 0.f, 0.f);
    int e = beg;
    for (; e + 3 < end; e += 4) {
        int s0 = g_colidx[e + 0];
        int s1 = g_colidx[e + 1];
        int s2 = g_colidx[e + 2];
        int s3 = g_colidx[e + 3];
        uint2 u0 = __ldg((const uint2*)(g_hh + (size_t)s0 * DF) + lane);
        uint2 u1 = __ldg((const uint2*)(g_hh + (size_t)s1 * DF) + lane);
        uint2 u2 = __ldg((const uint2*)(g_hh + (size_t)s2 * DF) + lane);
        uint2 u3 = __ldg((const uint2*)(g_hh + (size_t)s3 * DF) + lane);
        float2 a0 = __half22float2(*(__half2*)&u0.x), b0 = __half22float2(*(__half2*)&u0.y);
        float2 a1 = __half22float2(*(__half2*)&u1.x), b1 = __half22float2(*(__half2*)&u1.y);
        float2 a2 = __half22float2(*(__half2*)&u2.x), b2 = __half22float2(*(__half2*)&u2.y);
        float2 a3 = __half22float2(*(__half2*)&u3.x), b3 = __half22float2(*(__half2*)&u3.y);
        acc.x += (a0.x + a1.x) + (a2.x + a3.x);
        acc.y += (a0.y + a1.y) + (a2.y + a3.y);
        acc.z += (b0.x + b1.x) + (b2.x + b3.x);
        acc.w += (b0.y + b1.y) + (b2.y + b3.y);
    }
    for (; e < end; e++) {
        int s0 = g_colidx[e];
        uint2 u0 = __ldg((const uint2*)(g_hh + (size_t)s0 * DF) + lane);
        float2 a0 = __half22float2(*(__half2*)&u0.x), b0 = __half22float2(*(__half2*)&u0.y);
        acc.x += a0.x; acc.y += a0.y; acc.z += b0.x; acc.w += b0.y;
    }
    *((float4*)(g_agg + (size_t)gwarp * DF) + lane) = acc;
}

// ======================= tf32 mma.sync GEMM ================================
// Per CTA: 128 rows out = [g_agg | root] (K=256) @ WT^T (N=128), + bias, ReLU.
// When do_relu (layers 0/1), also writes fp16 mirror g_hh for the next agg.
#define GSTR 36

__global__ void __launch_bounds__(256) k_gemm_mma(
    const float* __restrict__ xext, int root_sel, int out_sel, int layer,
    const float* __restrict__ bias, int do_relu)
{
    __shared__ uint32_t sA[128 * GSTR];   // [m][k] tf32 bits
    __shared__ uint32_t sB[128 * GSTR];   // [n][k] tf32 bits

    const float* Aroot = (root_sel == 0) ? xext : (root_sel == 1 ? g_h0 : g_h1);
    float* out = (out_sel == 0) ? g_h0 : g_h1;

    int tid = threadIdx.x;
    int wid = tid >> 5;
    int lane = tid & 31;
    int row0 = blockIdx.x * 128;
    int wm = wid & 3;
    int wn = wid >> 2;
    int lq = lane >> 2;
    int lr = lane & 3;

    const float* Bsrc = &g_WT[layer][0][0];

    float acc[2][8][4];
    #pragma unroll
    for (int mt = 0; mt < 2; mt++)
        #pragma unroll
        for (int nt = 0; nt < 8; nt++)
            #pragma unroll
            for (int q = 0; q < 4; q++) acc[mt][nt][q] = 0.f;

    for (int c = 0; c < 8; c++) {
        int kbase = c * 32;
        const float* Asrc = (kbase < 128) ? g_agg : Aroot;
        int acol = kbase & 127;

        #pragma unroll
        for (int it = 0; it < 4; it++) {
            int idx = it * 256 + tid;
            int r = idx >> 3, c4 = idx & 7;
            int grow = row0 + r;
            float4 v = make_float4(0.f, 0.f, 0.f, 0.f);
            if (grow < N_NODES)
                v = *(const float4*)(Asrc + (size_t)grow * DF + acol + c4 * 4);
            uint4 p;
            p.x = f2tf32(v.x); p.y = f2tf32(v.y);
            p.z = f2tf32(v.z); p.w = f2tf32(v.w);
            *(uint4*)&sA[r * GSTR + c4 * 4] = p;
        }
        #pragma unroll
        for (int it = 0; it < 4; it++) {
            int idx = it * 256 + tid;
            int n = idx >> 3, c4 = idx & 7;
            float4 v = *(const float4*)(Bsrc + (size_t)n * 256 + kbase + c4 * 4);
            uint4 p;
            p.x = f2tf32(v.x); p.y = f2tf32(v.y);
            p.z = f2tf32(v.z); p.w = f2tf32(v.w);
            *(uint4*)&sB[n * GSTR + c4 * 4] = p;
        }
        __syncthreads();

        #pragma unroll
        for (int ks = 0; ks < 4; ks++) {
            int k0 = ks * 8;
            uint32_t a[2][4];
            #pragma unroll
            for (int mt = 0; mt < 2; mt++) {
                int mrow = wm * 32 + mt * 16;
                a[mt][0] = sA[(mrow + lq    ) * GSTR + k0 + lr    ];
                a[mt][1] = sA[(mrow + lq + 8) * GSTR + k0 + lr    ];
                a[mt][2] = sA[(mrow + lq    ) * GSTR + k0 + lr + 4];
                a[mt][3] = sA[(mrow + lq + 8) * GSTR + k0 + lr + 4];
            }
            #pragma unroll
            for (int nt = 0; nt < 8; nt++) {
                int ncol = wn * 64 + nt * 8;
                uint32_t b0 = sB[(ncol + lq) * GSTR + k0 + lr    ];
                uint32_t b1 = sB[(ncol + lq) * GSTR + k0 + lr + 4];
                MMA_TF32(acc[0][nt], a[0], b0, b1);
                MMA_TF32(acc[1][nt], a[1], b0, b1);
            }
        }
        __syncthreads();
    }

    #pragma unroll
    for (int mt = 0; mt < 2; mt++) {
        int r_lo = row0 + wm * 32 + mt * 16 + lq;
        int r_hi = r_lo + 8;
        #pragma unroll
        for (int nt = 0; nt < 8; nt++) {
            int col = wn * 64 + nt * 8 + lr * 2;
            float bx = bias[col], by = bias[col + 1];
            float2 lo, hi;
            lo.x = acc[mt][nt][0] + bx; lo.y = acc[mt][nt][1] + by;
            hi.x = acc[mt][nt][2] + bx; hi.y = acc[mt][nt][3] + by;
            if (do_relu) {
                lo.x = fmaxf(lo.x, 0.f); lo.y = fmaxf(lo.y, 0.f);
                hi.x = fmaxf(hi.x, 0.f); hi.y = fmaxf(hi.y, 0.f);
            }
            if (r_lo < N_NODES) {
                *(float2*)(out + (size_t)r_lo * DF + col) = lo;
                if (do_relu)
                    *(__half2*)(g_hh + (size_t)r_lo * DF + col) = __floats2half2_rn(lo.x, lo.y);
            }
            if (r_hi < N_NODES) {
                *(float2*)(out + (size_t)r_hi * DF + col) = hi;
                if (do_relu)
                    *(__half2*)(g_hh + (size_t)r_hi * DF + col) = __floats2half2_rn(hi.x, hi.y);
            }
        }
    }
}

// ======================= pool (run-combining, batch is sorted) =============
#define POOL_NPT 8
__global__ void k_pool(const int* __restrict__ batch) {
    int idx = blockIdx.x * blockDim.x + threadIdx.x;
    const int NGRP = N_NODES / POOL_NPT;     // 5000
    if (idx >= NGRP * 32) return;
    int grp = idx >> 5;
    int c = (idx & 31) * 4;
    int n0 = grp * POOL_NPT;
    int is64 = g_is64;

    int curg = -1;
    float4 m = make_float4(0.f, 0.f, 0.f, 0.f);
    #pragma unroll
    for (int i = 0; i < POOL_NPT; i++) {
        int node = n0 + i;
        int g = is64 ? batch[2 * node] : batch[node];
        float4 v = *(const float4*)(g_h0 + (size_t)node * DF + c);
        if (g != curg) {
            if (curg >= 0) {
                unsigned* o = &g_outmax[curg * DF + c];
                atomicMax(o + 0, enc_f(m.x));
                atomicMax(o + 1, enc_f(m.y));
                atomicMax(o + 2, enc_f(m.z));
                atomicMax(o + 3, enc_f(m.w));
            }
            curg = g; m = v;
        } else {
            m.x = fmaxf(m.x, v.x); m.y = fmaxf(m.y, v.y);
            m.z = fmaxf(m.z, v.z); m.w = fmaxf(m.w, v.w);
        }
    }
    unsigned* o = &g_outmax[curg * DF + c];
    atomicMax(o + 0, enc_f(m.x));
    atomicMax(o + 1, enc_f(m.y));
    atomicMax(o + 2, enc_f(m.z));
    atomicMax(o + 3, enc_f(m.w));
}

__global__ void k_decode(float* __restrict__ out) {
    int i = blockIdx.x * blockDim.x + threadIdx.x;
    if (i < N_GRAPHS * DF) out[i] = dec_f(g_outmax[i]);
}

// ===========================================================================
extern "C" void kernel_launch(void* const* d_in, const int* in_sizes, int n_in,
                              void* d_out, int out_size) {
    const float* x      = (const float*)d_in[0];
    const int*   edges  = (const int*)  d_in[1];   // int32 or int64 (probed)
    const int*   batch  = (const int*)  d_in[2];
    const float* Wrel0  = (const float*)d_in[3];
    const float* brel0  = (const float*)d_in[4];
    const float* Wroot0 = (const float*)d_in[5];
    const float* Wrel1  = (const float*)d_in[6];
    const float* brel1  = (const float*)d_in[7];
    const float* Wroot1 = (const float*)d_in[8];
    const float* Wrel2  = (const float*)d_in[9];
    const float* brel2  = (const float*)d_in[10];
    const float* Wroot2 = (const float*)d_in[11];
    float* out = (float*)d_out;

    // init covers the largest range: x->half (2.56M), so grid = 10000 blocks
    k_init<<<N_NODES * DF / 2 / 256, 256>>>(edges, x, Wrel0, Wroot0, Wrel1, Wroot1, Wrel2, Wroot2);
    k_count<<<N_EDGES / 256, 256>>>(edges);
    k_scan_part<<<SCAN_BLK, 256>>>();
    k_scan_top<<<1, 256>>>();
    k_scan_wr<<<SCAN_BLK, 256>>>();
    k_fill<<<N_EDGES / 256, 256>>>(edges);

    const int AGG_BLOCKS = N_NODES / 8;            // 8 warps/block, 1 node/warp
    const int GEMM_BLOCKS = (N_NODES + 127) / 128; // 313

    // layer 0: agg(hh=x16) -> gemm([agg|x]) -> h0 (ReLU) + hh=h0_16
    k_agg<<<AGG_BLOCKS, 256>>>();
    k_gemm_mma<<<GEMM_BLOCKS, 256>>>(x, 0, 0, 0, brel0, 1);
    // layer 1: agg(hh=h0_16) -> gemm([agg|h0]) -> h1 (ReLU) + hh=h1_16
    k_agg<<<AGG_BLOCKS, 256>>>();
    k_gemm_mma<<<GEMM_BLOCKS, 256>>>(x, 1, 1, 1, brel1, 1);
    // layer 2: agg(hh=h1_16) -> gemm([agg|h1]) -> h0 (no ReLU)
    k_agg<<<AGG_BLOCKS, 256>>>();
    k_gemm_mma<<<GEMM_BLOCKS, 256>>>(x, 2, 0, 2, brel2, 0);

    // pool + decode
    k_pool<<<(N_NODES / POOL_NPT * 32 + 255) / 256, 256>>>(batch);
    k_decode<<<(N_GRAPHS * DF + 255) / 256, 256>>>(out);
}